// round 13
// baseline (speedup 1.0000x reference)
#include <cuda_runtime.h>
#include <cstddef>

#define TSTEPS 512
#define BATCH  512
#define NUDIM  64
#define NXDIM  128
#define NVDIM  256
#define NYDIM  64
#define RPC    4
#define NCTA   128
#define NTHR   512

// ---------------- packed transposed weights (built once per launch) ----------
// W4[k4 * J + j].q = W[j][4*k4 + q]   (J outputs, K contraction)
__device__ float4 g_C1T4 [32 * NVDIM];
__device__ float4 g_D12T4[16 * NVDIM];
__device__ float4 g_D22T4[16 * NYDIM];
__device__ float4 g_AT4  [32 * NXDIM];
__device__ float4 g_B1T4 [64 * NXDIM];
__device__ float4 g_B2T4 [16 * NXDIM];
__device__ float4 g_C2T4 [32 * NYDIM];
__device__ float4 g_D21T4[64 * NYDIM];
__device__ float4 g_D11P [64 * NVDIM];      // packed D11[j][k] over k (off-diag)
__device__ float  g_D11T [NVDIM * NVDIM];   // scalar transpose (prep only)

__global__ void prep_kernel(const float* __restrict__ A,  const float* __restrict__ B1,
                            const float* __restrict__ B2, const float* __restrict__ C1,
                            const float* __restrict__ C2, const float* __restrict__ D11,
                            const float* __restrict__ D12,const float* __restrict__ D21,
                            const float* __restrict__ D22)
{
    int id = blockIdx.x * blockDim.x + threadIdx.x;
    int off = 0;
#define XP4(dst, src, J, K)                                                  \
    if (id < off + (J) * (K) / 4) {                                          \
        int i = id - off; int k4 = i / (J); int j = i % (J);                 \
        const float* p = (src) + (size_t)j * (K) + 4 * k4;                   \
        dst[i] = make_float4(p[0], p[1], p[2], p[3]); return;                \
    } off += (J) * (K) / 4;
    XP4(g_C1T4,  C1,  NVDIM, NXDIM)
    XP4(g_D12T4, D12, NVDIM, NUDIM)
    XP4(g_D22T4, D22, NYDIM, NUDIM)
    XP4(g_AT4,   A,   NXDIM, NXDIM)
    XP4(g_B1T4,  B1,  NXDIM, NVDIM)
    XP4(g_B2T4,  B2,  NXDIM, NUDIM)
    XP4(g_C2T4,  C2,  NYDIM, NXDIM)
    XP4(g_D21T4, D21, NYDIM, NVDIM)
    XP4(g_D11P,  D11, NVDIM, NVDIM)
#undef XP4
    if (id < off + NVDIM * NVDIM) {
        int i = id - off; int k = i / NVDIM; int j = i % NVDIM;
        g_D11T[i] = D11[(size_t)j * NVDIM + k];
    }
}

// panel start offsets (float4 units) in the packed off-diag triangle
#define OFFP0 0
#define OFFP1 1792
#define OFFP2 3328
#define OFFP3 4608
#define OFFP4 5632
#define OFFP5 6400
#define OFFP6 6912
#define OFFD_TOT 7168

// ---------------- shared memory (~181 KB) ----------------
struct Smem {
    float4 offd[OFFD_TOT];        // 114.7 KB packed strictly-lower off-diag D11
    float  diagblk[8][32 * 33];   //  33.8 KB padded 32x32 diag blocks
    float  diagc[8][4][32];       //   4 KB packed 8x8 strictly-lower coefs
    float4 xk[2][NXDIM];          // state, float4 across 4 rows
    float4 w[NVDIM];              // equilibrium solution
    float4 uu[2][NUDIM];          // double-buffered input tile
    float  bblk[8][32][4];        // per-panel handoff (no reuse races)
    unsigned cntA[8];             // owner arrivals  (64 per panel per step)
    unsigned cntW[8];             // solver arrivals (128 per panel per step)
    float4 xpart[3][NXDIM];       // phase-C x partials
    float4 ypart[7][NYDIM];       // phase-C y partials
};

#define FMA4C(a0,a1,a2,a3,c,v) do {                       \
    a0 = fmaf((c), (v).x, a0); a1 = fmaf((c), (v).y, a1); \
    a2 = fmaf((c), (v).z, a2); a3 = fmaf((c), (v).w, a3); } while (0)

__device__ __forceinline__ unsigned smem_u32(const void* p) {
    return (unsigned)__cvta_generic_to_shared(p);
}
__device__ __forceinline__ void red_release(unsigned addr) {
    asm volatile("red.release.cta.shared.add.u32 [%0], 1;" :: "r"(addr) : "memory");
}
__device__ __forceinline__ void spin_ge(unsigned addr, unsigned target) {
    unsigned v;
    do {
        asm volatile("ld.acquire.cta.shared.u32 %0, [%1];" : "=r"(v) : "r"(addr) : "memory");
    } while (v < target);
}

__global__ void __launch_bounds__(NTHR, 1)
ren_kernel(const float* __restrict__ x0, const float* __restrict__ u,
           const float* __restrict__ D11,
           const float* __restrict__ bx, const float* __restrict__ bv,
           const float* __restrict__ by, float* __restrict__ out)
{
    extern __shared__ char smem_raw[];
    Smem& s = *reinterpret_cast<Smem*>(smem_raw);
    const int tid  = threadIdx.x;
    const int lane = tid & 31;
    const int wid  = tid >> 5;
    const int row0 = blockIdx.x * RPC;
    const int j    = tid & 255;   // v-feature owned in phases A/B
    const int h    = tid >> 8;    // row-pair selector
    const int OFFP[8] = {OFFP0, OFFP1, OFFP2, OFFP3, OFFP4, OFFP5, OFFP6, OFFD_TOT};

    // ---- one-time staging ----
#pragma unroll
    for (int p = 0; p < 7; p++) {
        const int W = 224 - 32 * p;
        for (int i = tid; i < 8 * W; i += NTHR) {
            int g2 = i / W, jp = i - g2 * W;
            s.offd[OFFP[p] + i] = g_D11P[(p * 8 + g2) * NVDIM + (32 * (p + 1) + jp)];
        }
    }
    for (int i = tid; i < 8 * 32 * 32; i += NTHR) {   // padded diag blocks
        int p = i >> 10, l = (i >> 5) & 31, q = i & 31;
        s.diagblk[p][l * 33 + q] = D11[(size_t)(32 * p + l) * NVDIM + 32 * p + q];
    }
    if (tid < 32) {                 // packed 8x8 strictly-lower group coefs
        int blk = tid >> 2, g = tid & 3;
        int base = blk * 32 + g * 8, idx = 0;
        for (int ii = 1; ii < 8; ii++)
            for (int jj = 0; jj < ii; jj++)
                s.diagc[blk][g][idx++] = D11[(size_t)(base + ii) * NVDIM + (base + jj)];
    }
    for (int i = tid; i < RPC * NXDIM; i += NTHR) {   // initial state
        int r = i >> 7, k = i & 127;
        ((float*)s.xk[0])[k * 4 + r] = x0[(size_t)(row0 + r) * NXDIM + k];
    }
    if (tid < 8) { s.cntA[tid] = 0; s.cntW[tid] = 0; }
    const float bvr = bv[j];
    const float bxr = bx[tid & 127];
    const float byr = by[tid & 63];
    const unsigned cA = smem_u32(&s.cntA[0]);
    const unsigned cW = smem_u32(&s.cntW[0]);

    float ureg = 0.f;               // prefetch u(0)
    if (tid < 256) {
        int r = tid >> 6, k = tid & 63;
        ureg = u[((size_t)0 * BATCH + row0 + r) * NUDIM + k];
    }
    __syncthreads();

    float* yout = out + (size_t)BATCH * NXDIM;
    int cur = 0;

    for (int t = 0; t < TSTEPS; t++) {
        const int ub = t & 1;
        if (tid < 256) {            // commit u(t), prefetch u(t+1)
            int r = tid >> 6, k = tid & 63;
            ((float*)s.uu[ub])[k * 4 + r] = ureg;
            int tn = (t + 1 < TSTEPS) ? t + 1 : t;
            ureg = u[((size_t)tn * BATCH + row0 + r) * NUDIM + k];
        }
        __syncthreads();            // (1) u + state visible; prev step fully done
        const int nxt = cur ^ 1;
        const float4* xc = s.xk[cur];
        const float4* uc = s.uu[ub];
        const unsigned stampA = 64u  * (unsigned)(t + 1);
        const unsigned stampW = 128u * (unsigned)(t + 1);

        // ---- phase A: b = bv + C1 x + D12 u ----
        float ba0 = bvr, ba1 = bvr;
#pragma unroll 4
        for (int k4 = 0; k4 < 32; k4++) {
            float4 c = g_C1T4[k4 * NVDIM + j];
            const float2* xp = (const float2*)&xc[4 * k4];
            float2 v0 = xp[0 + h], v1 = xp[2 + h], v2 = xp[4 + h], v3 = xp[6 + h];
            ba0 = fmaf(c.x, v0.x, ba0); ba1 = fmaf(c.x, v0.y, ba1);
            ba0 = fmaf(c.y, v1.x, ba0); ba1 = fmaf(c.y, v1.y, ba1);
            ba0 = fmaf(c.z, v2.x, ba0); ba1 = fmaf(c.z, v2.y, ba1);
            ba0 = fmaf(c.w, v3.x, ba0); ba1 = fmaf(c.w, v3.y, ba1);
        }
#pragma unroll 4
        for (int k4 = 0; k4 < 16; k4++) {
            float4 c = g_D12T4[k4 * NVDIM + j];
            const float2* up = (const float2*)&uc[4 * k4];
            float2 v0 = up[0 + h], v1 = up[2 + h], v2 = up[4 + h], v3 = up[6 + h];
            ba0 = fmaf(c.x, v0.x, ba0); ba1 = fmaf(c.x, v0.y, ba1);
            ba0 = fmaf(c.y, v1.x, ba0); ba1 = fmaf(c.y, v1.y, ba1);
            ba0 = fmaf(c.z, v2.x, ba0); ba1 = fmaf(c.z, v2.y, ba1);
            ba0 = fmaf(c.w, v3.x, ba0); ba1 = fmaf(c.w, v3.y, ba1);
        }

        // ---- phase B: triangular ReLU equilibrium, flag-synchronized ----
#pragma unroll
        for (int p = 0; p < 8; p++) {
            const int base = p * 32;
            if (j >= base && j < base + 32) {      // owner: hand off b(panel p)
                *(float2*)&s.bblk[p][j - base][2 * h] = make_float2(ba0, ba1);
                red_release(cA + 4u * p);
            }
            if (wid < 4) {                         // solver: warp r solves row r
                const int r = wid;
                spin_ge(cA + 4u * p, stampA);
                float dcl[32];
#pragma unroll
                for (int q = 0; q < 32; q++) dcl[q] = s.diagblk[p][lane * 33 + q];
                float bval = s.bblk[p][lane][r];
                float wmine = 0.f;
#pragma unroll
                for (int g = 0; g < 4; g++) {
                    const int q0 = g * 8;
                    float cg[28];
#pragma unroll
                    for (int q = 0; q < 28; q++) cg[q] = s.diagc[p][g][q];
                    float bg[8];
#pragma unroll
                    for (int q = 0; q < 8; q++)
                        bg[q] = __shfl_sync(0xffffffffu, bval, q0 + q);
                    float wloc[8];
#pragma unroll
                    for (int jj = 0; jj < 8; jj++) {   // redundant serial resolve
                        float wj = fmaxf(bg[jj], 0.f);
                        wloc[jj] = wj;
#pragma unroll
                        for (int ii = jj + 1; ii < 8; ii++)
                            bg[ii] = fmaf(cg[ii * (ii - 1) / 2 + jj], wj, bg[ii]);
                    }
                    if ((lane >> 3) == g) wmine = wloc[lane & 7];
                    float a0 = 0.f, a1 = 0.f;          // apply (upper coefs are 0)
                    a0 = fmaf(dcl[q0 + 0], wloc[0], a0); a1 = fmaf(dcl[q0 + 1], wloc[1], a1);
                    a0 = fmaf(dcl[q0 + 2], wloc[2], a0); a1 = fmaf(dcl[q0 + 3], wloc[3], a1);
                    a0 = fmaf(dcl[q0 + 4], wloc[4], a0); a1 = fmaf(dcl[q0 + 5], wloc[5], a1);
                    a0 = fmaf(dcl[q0 + 6], wloc[6], a0); a1 = fmaf(dcl[q0 + 7], wloc[7], a1);
                    bval += a0 + a1;
                }
                ((float*)&s.w[base + lane])[r] = wmine;
                red_release(cW + 4u * p);
            }
            if (j >= base + 32) {                  // consumer: rank-32 off-diag
                spin_ge(cW + 4u * p, stampW);
                const int W = 224 - 32 * p;
                const float4* cp = s.offd + OFFP[p] + (j - base - 32);
#pragma unroll
                for (int g2 = 0; g2 < 8; g2++) {
                    float4 c = cp[g2 * W];
                    const float2* wp = (const float2*)&s.w[base + 4 * g2];
                    float2 w0 = wp[0 + h], w1 = wp[2 + h], w2 = wp[4 + h], w3 = wp[6 + h];
                    ba0 = fmaf(c.x, w0.x, ba0); ba1 = fmaf(c.x, w0.y, ba1);
                    ba0 = fmaf(c.y, w1.x, ba0); ba1 = fmaf(c.y, w1.y, ba1);
                    ba0 = fmaf(c.z, w2.x, ba0); ba1 = fmaf(c.z, w2.y, ba1);
                    ba0 = fmaf(c.w, w3.x, ba0); ba1 = fmaf(c.w, w3.y, ba1);
                }
            }
        }

        // ---- phase C part 1: w-independent (A, B2, C2, D22) ----
        const int xj = tid & 127, xq = tid >> 7;      // 4 k-chunks
        float xa0, xa1, xa2, xa3;
        xa0 = xa1 = xa2 = xa3 = (xq == 0) ? bxr : 0.f;
#pragma unroll 4
        for (int i = 0; i < 8; i++) {                 // A: 32 k per chunk
            int k4 = xq * 8 + i;
            float4 c = g_AT4[k4 * NXDIM + xj];
            const float4* v = &xc[4 * k4];
            FMA4C(xa0, xa1, xa2, xa3, c.x, v[0]);
            FMA4C(xa0, xa1, xa2, xa3, c.y, v[1]);
            FMA4C(xa0, xa1, xa2, xa3, c.z, v[2]);
            FMA4C(xa0, xa1, xa2, xa3, c.w, v[3]);
        }
#pragma unroll
        for (int i = 0; i < 4; i++) {                 // B2: 16 k per chunk
            int k4 = xq * 4 + i;
            float4 c = g_B2T4[k4 * NXDIM + xj];
            const float4* v = &uc[4 * k4];
            FMA4C(xa0, xa1, xa2, xa3, c.x, v[0]);
            FMA4C(xa0, xa1, xa2, xa3, c.y, v[1]);
            FMA4C(xa0, xa1, xa2, xa3, c.z, v[2]);
            FMA4C(xa0, xa1, xa2, xa3, c.w, v[3]);
        }
        const int yj = tid & 63, yq = tid >> 6;       // 8 k-chunks
        float ya0, ya1, ya2, ya3;
        ya0 = ya1 = ya2 = ya3 = (yq == 0) ? byr : 0.f;
#pragma unroll
        for (int i = 0; i < 4; i++) {                 // C2: 16 k per chunk
            int k4 = yq * 4 + i;
            float4 c = g_C2T4[k4 * NYDIM + yj];
            const float4* v = &xc[4 * k4];
            FMA4C(ya0, ya1, ya2, ya3, c.x, v[0]);
            FMA4C(ya0, ya1, ya2, ya3, c.y, v[1]);
            FMA4C(ya0, ya1, ya2, ya3, c.z, v[2]);
            FMA4C(ya0, ya1, ya2, ya3, c.w, v[3]);
        }
#pragma unroll
        for (int i = 0; i < 2; i++) {                 // D22: 8 k per chunk
            int k4 = yq * 2 + i;
            float4 c = g_D22T4[k4 * NYDIM + yj];
            const float4* v = &uc[4 * k4];
            FMA4C(ya0, ya1, ya2, ya3, c.x, v[0]);
            FMA4C(ya0, ya1, ya2, ya3, c.y, v[1]);
            FMA4C(ya0, ya1, ya2, ya3, c.z, v[2]);
            FMA4C(ya0, ya1, ya2, ya3, c.w, v[3]);
        }

        // ---- phase C part 2: w-dependent (B1, D21) after all w ready ----
        spin_ge(cW + 4u * 7, stampW);
#pragma unroll 4
        for (int i = 0; i < 16; i++) {                // B1: 64 k per chunk
            int k4 = xq * 16 + i;
            float4 c = g_B1T4[k4 * NXDIM + xj];
            const float4* v = &s.w[4 * k4];
            FMA4C(xa0, xa1, xa2, xa3, c.x, v[0]);
            FMA4C(xa0, xa1, xa2, xa3, c.y, v[1]);
            FMA4C(xa0, xa1, xa2, xa3, c.z, v[2]);
            FMA4C(xa0, xa1, xa2, xa3, c.w, v[3]);
        }
        if (xq > 0) s.xpart[xq - 1][xj] = make_float4(xa0, xa1, xa2, xa3);
#pragma unroll 4
        for (int i = 0; i < 8; i++) {                 // D21: 32 k per chunk
            int k4 = yq * 8 + i;
            float4 c = g_D21T4[k4 * NYDIM + yj];
            const float4* v = &s.w[4 * k4];
            FMA4C(ya0, ya1, ya2, ya3, c.x, v[0]);
            FMA4C(ya0, ya1, ya2, ya3, c.y, v[1]);
            FMA4C(ya0, ya1, ya2, ya3, c.z, v[2]);
            FMA4C(ya0, ya1, ya2, ya3, c.w, v[3]);
        }
        if (yq > 0) s.ypart[yq - 1][yj] = make_float4(ya0, ya1, ya2, ya3);
        __syncthreads();            // (2) partials visible

        // ---- combines ----
        if (xq == 0) {
#pragma unroll
            for (int pq = 0; pq < 3; pq++) {
                float4 pp = s.xpart[pq][xj];
                xa0 += pp.x; xa1 += pp.y; xa2 += pp.z; xa3 += pp.w;
            }
            s.xk[nxt][xj] = make_float4(xa0, xa1, xa2, xa3);
        }
        if (yq == 0) {
#pragma unroll
            for (int pq = 0; pq < 7; pq++) {
                float4 pp = s.ypart[pq][yj];
                ya0 += pp.x; ya1 += pp.y; ya2 += pp.z; ya3 += pp.w;
            }
            float* yo = yout + ((size_t)t * BATCH + row0) * NYDIM + yj;
            yo[0 * NYDIM] = ya0;
            yo[1 * NYDIM] = ya1;
            yo[2 * NYDIM] = ya2;
            yo[3 * NYDIM] = ya3;
        }
        cur ^= 1;
    }

    // ---- final state x1 ----
    __syncthreads();
    if (tid < NXDIM) {
        float4 v = s.xk[cur][tid];
        out[(size_t)(row0 + 0) * NXDIM + tid] = v.x;
        out[(size_t)(row0 + 1) * NXDIM + tid] = v.y;
        out[(size_t)(row0 + 2) * NXDIM + tid] = v.z;
        out[(size_t)(row0 + 3) * NXDIM + tid] = v.w;
    }
}

extern "C" void kernel_launch(void* const* d_in, const int* in_sizes, int n_in,
                              void* d_out, int out_size)
{
    const float* x0  = (const float*)d_in[0];
    const float* u   = (const float*)d_in[1];
    const float* A   = (const float*)d_in[2];
    const float* B1  = (const float*)d_in[3];
    const float* B2  = (const float*)d_in[4];
    const float* C1  = (const float*)d_in[5];
    const float* C2  = (const float*)d_in[6];
    const float* D11 = (const float*)d_in[7];
    const float* D12 = (const float*)d_in[8];
    const float* D21 = (const float*)d_in[9];
    const float* D22 = (const float*)d_in[10];
    const float* bx  = (const float*)d_in[11];
    const float* bv  = (const float*)d_in[12];
    const float* by  = (const float*)d_in[13];
    float* out = (float*)d_out;

    prep_kernel<<<452, 256>>>(A, B1, B2, C1, C2, D11, D12, D21, D22);

    size_t smem = sizeof(Smem);
    cudaFuncSetAttribute(ren_kernel, cudaFuncAttributeMaxDynamicSharedMemorySize,
                         (int)smem);
    ren_kernel<<<NCTA, NTHR, smem>>>(x0, u, D11, bx, bv, by, out);
}

// round 14
// speedup vs baseline: 1.1638x; 1.1638x over previous
#include <cuda_runtime.h>
#include <cstddef>

#define TSTEPS 512
#define BATCH  512
#define NUDIM  64
#define NXDIM  128
#define NVDIM  256
#define NYDIM  64
#define RPC    4
#define NCTA   128
#define NTHR   512

// ---------------- packed transposed weights (built once per launch) ----------
// W4[k4 * J + j].q = W[j][4*k4 + q]   (J outputs, K contraction)
__device__ float4 g_C1T4 [32 * NVDIM];
__device__ float4 g_D12T4[16 * NVDIM];
__device__ float4 g_D22T4[16 * NYDIM];
__device__ float4 g_AT4  [32 * NXDIM];
__device__ float4 g_B1T4 [64 * NXDIM];
__device__ float4 g_B2T4 [16 * NXDIM];
__device__ float4 g_C2T4 [32 * NYDIM];
__device__ float4 g_D21T4[64 * NYDIM];
__device__ float4 g_D11P [64 * NVDIM];      // packed D11[j][k] over k (off-diag)
__device__ float  g_D11T [NVDIM * NVDIM];   // scalar transpose (prep only)

__global__ void prep_kernel(const float* __restrict__ A,  const float* __restrict__ B1,
                            const float* __restrict__ B2, const float* __restrict__ C1,
                            const float* __restrict__ C2, const float* __restrict__ D11,
                            const float* __restrict__ D12,const float* __restrict__ D21,
                            const float* __restrict__ D22)
{
    int id = blockIdx.x * blockDim.x + threadIdx.x;
    int off = 0;
#define XP4(dst, src, J, K)                                                  \
    if (id < off + (J) * (K) / 4) {                                          \
        int i = id - off; int k4 = i / (J); int j = i % (J);                 \
        const float* p = (src) + (size_t)j * (K) + 4 * k4;                   \
        dst[i] = make_float4(p[0], p[1], p[2], p[3]); return;                \
    } off += (J) * (K) / 4;
    XP4(g_C1T4,  C1,  NVDIM, NXDIM)
    XP4(g_D12T4, D12, NVDIM, NUDIM)
    XP4(g_D22T4, D22, NYDIM, NUDIM)
    XP4(g_AT4,   A,   NXDIM, NXDIM)
    XP4(g_B1T4,  B1,  NXDIM, NVDIM)
    XP4(g_B2T4,  B2,  NXDIM, NUDIM)
    XP4(g_C2T4,  C2,  NYDIM, NXDIM)
    XP4(g_D21T4, D21, NYDIM, NVDIM)
    XP4(g_D11P,  D11, NVDIM, NVDIM)
#undef XP4
    if (id < off + NVDIM * NVDIM) {
        int i = id - off; int k = i / NVDIM; int j = i % NVDIM;
        g_D11T[i] = D11[(size_t)j * NVDIM + k];
    }
}

// panel start offsets (float4 units) in the packed off-diag triangle
#define OFFP0 0
#define OFFP1 1792
#define OFFP2 3328
#define OFFP3 4608
#define OFFP4 5632
#define OFFP5 6400
#define OFFP6 6912
#define OFFD_TOT 7168

// ---------------- shared memory (~190 KB) ----------------
struct Smem {
    float4 offd[OFFD_TOT];        // 114.7 KB packed strictly-lower off-diag D11
    float  diagblk[8][32 * 33];   //  33.8 KB padded 32x32 diag blocks
    float  diagc[8][4][32];       //   4 KB packed 8x8 strictly-lower coefs
    float4 xk[2][NXDIM];          // state, float4 across 4 rows
    float4 w[NVDIM];              // equilibrium solution
    float4 uu[2][NUDIM];          // double-buffered input tile
    float4 bblk2[8][2][32];       // per-panel, per-h partial handoff (8 KB)
    float  bvs[NVDIM];            // staged bv
    float4 xpart[3][NXDIM];       // phase-C x partials
    float4 ypart[7][NYDIM];       // phase-C y partials
};

#define FMA4C(a0,a1,a2,a3,c,v) do {                       \
    a0 = fmaf((c), (v).x, a0); a1 = fmaf((c), (v).y, a1); \
    a2 = fmaf((c), (v).z, a2); a3 = fmaf((c), (v).w, a3); } while (0)

__global__ void __launch_bounds__(NTHR, 1)
ren_kernel(const float* __restrict__ x0, const float* __restrict__ u,
           const float* __restrict__ D11,
           const float* __restrict__ bx, const float* __restrict__ bv,
           const float* __restrict__ by, float* __restrict__ out)
{
    extern __shared__ char smem_raw[];
    Smem& s = *reinterpret_cast<Smem*>(smem_raw);
    const int tid  = threadIdx.x;
    const int lane = tid & 31;
    const int wid  = tid >> 5;
    const int row0 = blockIdx.x * RPC;
    const int j    = tid & 255;   // v-feature owned in phases A/B
    const int h    = tid >> 8;    // k-split / g2-split selector
    const int OFFP[8] = {OFFP0, OFFP1, OFFP2, OFFP3, OFFP4, OFFP5, OFFP6, OFFD_TOT};

    // ---- one-time staging ----
#pragma unroll
    for (int p = 0; p < 7; p++) {
        const int W = 224 - 32 * p;
        for (int i = tid; i < 8 * W; i += NTHR) {
            int g2 = i / W, jp = i - g2 * W;
            s.offd[OFFP[p] + i] = g_D11P[(p * 8 + g2) * NVDIM + (32 * (p + 1) + jp)];
        }
    }
    for (int i = tid; i < 8 * 32 * 32; i += NTHR) {   // padded diag blocks
        int p = i >> 10, l = (i >> 5) & 31, q = i & 31;
        s.diagblk[p][l * 33 + q] = D11[(size_t)(32 * p + l) * NVDIM + 32 * p + q];
    }
    if (tid < 32) {                 // packed 8x8 strictly-lower group coefs
        int blk = tid >> 2, g = tid & 3;
        int base = blk * 32 + g * 8, idx = 0;
        for (int ii = 1; ii < 8; ii++)
            for (int jj = 0; jj < ii; jj++)
                s.diagc[blk][g][idx++] = D11[(size_t)(base + ii) * NVDIM + (base + jj)];
    }
    for (int i = tid; i < RPC * NXDIM; i += NTHR) {   // initial state
        int r = i >> 7, k = i & 127;
        ((float*)s.xk[0])[k * 4 + r] = x0[(size_t)(row0 + r) * NXDIM + k];
    }
    if (tid < NVDIM) s.bvs[tid] = bv[tid];
    const float bxr = bx[tid & 127];
    const float byr = by[tid & 63];

    float ureg = 0.f;               // prefetch u(0)
    if (tid < 256) {
        int r = tid >> 6, k = tid & 63;
        ureg = u[((size_t)0 * BATCH + row0 + r) * NUDIM + k];
    }
    __syncthreads();

    float* yout = out + (size_t)BATCH * NXDIM;
    int cur = 0;

    for (int t = 0; t < TSTEPS; t++) {
        const int ub = t & 1;
        if (tid < 256) {            // commit u(t), prefetch u(t+1)
            int r = tid >> 6, k = tid & 63;
            ((float*)s.uu[ub])[k * 4 + r] = ureg;
            int tn = (t + 1 < TSTEPS) ? t + 1 : t;
            ureg = u[((size_t)tn * BATCH + row0 + r) * NUDIM + k];
        }
        __syncthreads();
        const int nxt = cur ^ 1;
        const float4* xc = s.xk[cur];
        const float4* uc = s.uu[ub];

        // ---- phase A (k-split dedup): each weight read ONCE, all 4 rows ----
        float pa0 = 0.f, pa1 = 0.f, pa2 = 0.f, pa3 = 0.f;
        if (h == 0) {
#pragma unroll 4
            for (int k4 = 0; k4 < 24; k4++) {
                float4 c = g_C1T4[k4 * NVDIM + j];
                const float4* v = &xc[4 * k4];
                FMA4C(pa0, pa1, pa2, pa3, c.x, v[0]);
                FMA4C(pa0, pa1, pa2, pa3, c.y, v[1]);
                FMA4C(pa0, pa1, pa2, pa3, c.z, v[2]);
                FMA4C(pa0, pa1, pa2, pa3, c.w, v[3]);
            }
        } else {
#pragma unroll 4
            for (int k4 = 24; k4 < 32; k4++) {
                float4 c = g_C1T4[k4 * NVDIM + j];
                const float4* v = &xc[4 * k4];
                FMA4C(pa0, pa1, pa2, pa3, c.x, v[0]);
                FMA4C(pa0, pa1, pa2, pa3, c.y, v[1]);
                FMA4C(pa0, pa1, pa2, pa3, c.z, v[2]);
                FMA4C(pa0, pa1, pa2, pa3, c.w, v[3]);
            }
#pragma unroll 4
            for (int k4 = 0; k4 < 16; k4++) {
                float4 c = g_D12T4[k4 * NVDIM + j];
                const float4* v = &uc[4 * k4];
                FMA4C(pa0, pa1, pa2, pa3, c.x, v[0]);
                FMA4C(pa0, pa1, pa2, pa3, c.y, v[1]);
                FMA4C(pa0, pa1, pa2, pa3, c.z, v[2]);
                FMA4C(pa0, pa1, pa2, pa3, c.w, v[3]);
            }
        }
        // off-diag partial (this thread's g2 half), all 4 rows
        float oa0 = 0.f, oa1 = 0.f, oa2 = 0.f, oa3 = 0.f;

        // ---- phase B: blocked triangular ReLU equilibrium ----
#pragma unroll
        for (int p = 0; p < 8; p++) {
            const int base = p * 32;
            if (j >= base && j < base + 32)   // owner: write partial (pa + oa)
                s.bblk2[p][h][j - base] =
                    make_float4(pa0 + oa0, pa1 + oa1, pa2 + oa2, pa3 + oa3);
            __syncthreads();                       // B1: partials visible

            if (wid < 4) {                         // warp r solves row r
                const int r = wid;
                float dcl[32];                     // conflict-free padded reads
#pragma unroll
                for (int q = 0; q < 32; q++) dcl[q] = s.diagblk[p][lane * 33 + q];
                float bval = ((const float*)&s.bblk2[p][0][lane])[r]
                           + ((const float*)&s.bblk2[p][1][lane])[r]
                           + s.bvs[base + lane];
                float wmine = 0.f;
#pragma unroll
                for (int g = 0; g < 4; g++) {
                    const int q0 = g * 8;
                    float cg[28];
#pragma unroll
                    for (int q = 0; q < 28; q++) cg[q] = s.diagc[p][g][q];
                    float bg[8];
#pragma unroll
                    for (int q = 0; q < 8; q++)
                        bg[q] = __shfl_sync(0xffffffffu, bval, q0 + q);
                    float wloc[8];
#pragma unroll
                    for (int jj = 0; jj < 8; jj++) {   // redundant serial resolve
                        float wj = fmaxf(bg[jj], 0.f);
                        wloc[jj] = wj;
#pragma unroll
                        for (int ii = jj + 1; ii < 8; ii++)
                            bg[ii] = fmaf(cg[ii * (ii - 1) / 2 + jj], wj, bg[ii]);
                    }
                    if ((lane >> 3) == g) wmine = wloc[lane & 7];
                    float a0 = 0.f, a1 = 0.f;          // apply (upper coefs are 0)
                    a0 = fmaf(dcl[q0 + 0], wloc[0], a0); a1 = fmaf(dcl[q0 + 1], wloc[1], a1);
                    a0 = fmaf(dcl[q0 + 2], wloc[2], a0); a1 = fmaf(dcl[q0 + 3], wloc[3], a1);
                    a0 = fmaf(dcl[q0 + 4], wloc[4], a0); a1 = fmaf(dcl[q0 + 5], wloc[5], a1);
                    a0 = fmaf(dcl[q0 + 6], wloc[6], a0); a1 = fmaf(dcl[q0 + 7], wloc[7], a1);
                    bval += a0 + a1;
                }
                ((float*)&s.w[base + lane])[r] = wmine;
            }
            __syncthreads();                       // B2: w(p) visible

            if (j >= base + 32) {                  // consumer: HALF the g2 range
                const int W = 224 - 32 * p;
                const float4* cp = s.offd + OFFP[p] + (j - base - 32);
#pragma unroll
                for (int i = 0; i < 4; i++) {
                    const int g2 = 4 * h + i;
                    float4 c = cp[g2 * W];
                    const float4* wp = &s.w[base + 4 * g2];
                    FMA4C(oa0, oa1, oa2, oa3, c.x, wp[0]);
                    FMA4C(oa0, oa1, oa2, oa3, c.y, wp[1]);
                    FMA4C(oa0, oa1, oa2, oa3, c.z, wp[2]);
                    FMA4C(oa0, oa1, oa2, oa3, c.w, wp[3]);
                }
            }
        }

        // ---- phase C: x1 and y, k-split over thread groups ----
        const int xj = tid & 127, xq = tid >> 7;      // 4 k-chunks
        float xa0, xa1, xa2, xa3;
        xa0 = xa1 = xa2 = xa3 = (xq == 0) ? bxr : 0.f;
#pragma unroll 4
        for (int i = 0; i < 8; i++) {                 // A: 32 k per chunk
            int k4 = xq * 8 + i;
            float4 c = g_AT4[k4 * NXDIM + xj];
            const float4* v = &xc[4 * k4];
            FMA4C(xa0, xa1, xa2, xa3, c.x, v[0]);
            FMA4C(xa0, xa1, xa2, xa3, c.y, v[1]);
            FMA4C(xa0, xa1, xa2, xa3, c.z, v[2]);
            FMA4C(xa0, xa1, xa2, xa3, c.w, v[3]);
        }
#pragma unroll 4
        for (int i = 0; i < 16; i++) {                // B1: 64 k per chunk
            int k4 = xq * 16 + i;
            float4 c = g_B1T4[k4 * NXDIM + xj];
            const float4* v = &s.w[4 * k4];
            FMA4C(xa0, xa1, xa2, xa3, c.x, v[0]);
            FMA4C(xa0, xa1, xa2, xa3, c.y, v[1]);
            FMA4C(xa0, xa1, xa2, xa3, c.z, v[2]);
            FMA4C(xa0, xa1, xa2, xa3, c.w, v[3]);
        }
#pragma unroll
        for (int i = 0; i < 4; i++) {                 // B2: 16 k per chunk
            int k4 = xq * 4 + i;
            float4 c = g_B2T4[k4 * NXDIM + xj];
            const float4* v = &uc[4 * k4];
            FMA4C(xa0, xa1, xa2, xa3, c.x, v[0]);
            FMA4C(xa0, xa1, xa2, xa3, c.y, v[1]);
            FMA4C(xa0, xa1, xa2, xa3, c.z, v[2]);
            FMA4C(xa0, xa1, xa2, xa3, c.w, v[3]);
        }
        if (xq > 0) s.xpart[xq - 1][xj] = make_float4(xa0, xa1, xa2, xa3);

        const int yj = tid & 63, yq = tid >> 6;       // 8 k-chunks
        float ya0, ya1, ya2, ya3;
        ya0 = ya1 = ya2 = ya3 = (yq == 0) ? byr : 0.f;
#pragma unroll
        for (int i = 0; i < 4; i++) {                 // C2: 16 k per chunk
            int k4 = yq * 4 + i;
            float4 c = g_C2T4[k4 * NYDIM + yj];
            const float4* v = &xc[4 * k4];
            FMA4C(ya0, ya1, ya2, ya3, c.x, v[0]);
            FMA4C(ya0, ya1, ya2, ya3, c.y, v[1]);
            FMA4C(ya0, ya1, ya2, ya3, c.z, v[2]);
            FMA4C(ya0, ya1, ya2, ya3, c.w, v[3]);
        }
#pragma unroll 4
        for (int i = 0; i < 8; i++) {                 // D21: 32 k per chunk
            int k4 = yq * 8 + i;
            float4 c = g_D21T4[k4 * NYDIM + yj];
            const float4* v = &s.w[4 * k4];
            FMA4C(ya0, ya1, ya2, ya3, c.x, v[0]);
            FMA4C(ya0, ya1, ya2, ya3, c.y, v[1]);
            FMA4C(ya0, ya1, ya2, ya3, c.z, v[2]);
            FMA4C(ya0, ya1, ya2, ya3, c.w, v[3]);
        }
#pragma unroll
        for (int i = 0; i < 2; i++) {                 // D22: 8 k per chunk
            int k4 = yq * 2 + i;
            float4 c = g_D22T4[k4 * NYDIM + yj];
            const float4* v = &uc[4 * k4];
            FMA4C(ya0, ya1, ya2, ya3, c.x, v[0]);
            FMA4C(ya0, ya1, ya2, ya3, c.y, v[1]);
            FMA4C(ya0, ya1, ya2, ya3, c.z, v[2]);
            FMA4C(ya0, ya1, ya2, ya3, c.w, v[3]);
        }
        if (yq > 0) s.ypart[yq - 1][yj] = make_float4(ya0, ya1, ya2, ya3);
        __syncthreads();

        // ---- combines ----
        if (xq == 0) {
#pragma unroll
            for (int pq = 0; pq < 3; pq++) {
                float4 pp = s.xpart[pq][xj];
                xa0 += pp.x; xa1 += pp.y; xa2 += pp.z; xa3 += pp.w;
            }
            s.xk[nxt][xj] = make_float4(xa0, xa1, xa2, xa3);
        }
        if (yq == 0) {
#pragma unroll
            for (int pq = 0; pq < 7; pq++) {
                float4 pp = s.ypart[pq][yj];
                ya0 += pp.x; ya1 += pp.y; ya2 += pp.z; ya3 += pp.w;
            }
            float* yo = yout + ((size_t)t * BATCH + row0) * NYDIM + yj;
            yo[0 * NYDIM] = ya0;
            yo[1 * NYDIM] = ya1;
            yo[2 * NYDIM] = ya2;
            yo[3 * NYDIM] = ya3;
        }
        cur ^= 1;
    }

    // ---- final state x1 ----
    __syncthreads();
    if (tid < NXDIM) {
        float4 v = s.xk[cur][tid];
        out[(size_t)(row0 + 0) * NXDIM + tid] = v.x;
        out[(size_t)(row0 + 1) * NXDIM + tid] = v.y;
        out[(size_t)(row0 + 2) * NXDIM + tid] = v.z;
        out[(size_t)(row0 + 3) * NXDIM + tid] = v.w;
    }
}

extern "C" void kernel_launch(void* const* d_in, const int* in_sizes, int n_in,
                              void* d_out, int out_size)
{
    const float* x0  = (const float*)d_in[0];
    const float* u   = (const float*)d_in[1];
    const float* A   = (const float*)d_in[2];
    const float* B1  = (const float*)d_in[3];
    const float* B2  = (const float*)d_in[4];
    const float* C1  = (const float*)d_in[5];
    const float* C2  = (const float*)d_in[6];
    const float* D11 = (const float*)d_in[7];
    const float* D12 = (const float*)d_in[8];
    const float* D21 = (const float*)d_in[9];
    const float* D22 = (const float*)d_in[10];
    const float* bx  = (const float*)d_in[11];
    const float* bv  = (const float*)d_in[12];
    const float* by  = (const float*)d_in[13];
    float* out = (float*)d_out;

    prep_kernel<<<452, 256>>>(A, B1, B2, C1, C2, D11, D12, D21, D22);

    size_t smem = sizeof(Smem);
    cudaFuncSetAttribute(ren_kernel, cudaFuncAttributeMaxDynamicSharedMemorySize,
                         (int)smem);
    ren_kernel<<<NCTA, NTHR, smem>>>(x0, u, D11, bx, bv, by, out);
}

// round 15
// speedup vs baseline: 1.2073x; 1.0374x over previous
#include <cuda_runtime.h>
#include <cstddef>

#define TSTEPS 512
#define BATCH  512
#define NUDIM  64
#define NXDIM  128
#define NVDIM  256
#define NYDIM  64
#define RPC    4
#define NCTA   128
#define NTHR   768

// ---------------- packed weights (built once per launch) ----------
__device__ float4 g_C1T4 [32 * NVDIM];   // C1T4[k4*256+j].q = C1[j][4k4+q]
__device__ float4 g_D12T4[16 * NVDIM];
__device__ float4 g_D11P [64 * NVDIM];   // D11P[g*256+j].q = D11[j][4g+q]
__device__ float4 g_W4   [112 * 192];    // unified phase-C weights [k4][output]

__global__ void prep_kernel(const float* __restrict__ A,  const float* __restrict__ B1,
                            const float* __restrict__ B2, const float* __restrict__ C1,
                            const float* __restrict__ C2, const float* __restrict__ D11,
                            const float* __restrict__ D12,const float* __restrict__ D21,
                            const float* __restrict__ D22)
{
    int id = blockIdx.x * blockDim.x + threadIdx.x;
    int off = 0;
#define XP4(dst, src, J, K)                                                  \
    if (id < off + (J) * (K) / 4) {                                          \
        int i = id - off; int k4 = i / (J); int j = i % (J);                 \
        const float* p = (src) + (size_t)j * (K) + 4 * k4;                   \
        dst[i] = make_float4(p[0], p[1], p[2], p[3]); return;                \
    } off += (J) * (K) / 4;
    XP4(g_C1T4,  C1,  NVDIM, NXDIM)
    XP4(g_D12T4, D12, NVDIM, NUDIM)
    XP4(g_D11P,  D11, NVDIM, NVDIM)
#undef XP4
    if (id < off + 112 * 192) {          // unified phase-C weights
        int i = id - off; int k4 = i / 192; int o = i % 192;
        const float* src;
        if (o < 128) {                   // x outputs: A | B1 | B2 over k
            if (k4 < 32)      src = A   + (size_t)o * NXDIM + 4 * k4;
            else if (k4 < 96) src = B1  + (size_t)o * NVDIM + 4 * (k4 - 32);
            else              src = B2  + (size_t)o * NUDIM + 4 * (k4 - 96);
        } else {                         // y outputs: C2 | D21 | D22
            int yo = o - 128;
            if (k4 < 32)      src = C2  + (size_t)yo * NXDIM + 4 * k4;
            else if (k4 < 96) src = D21 + (size_t)yo * NVDIM + 4 * (k4 - 32);
            else              src = D22 + (size_t)yo * NUDIM + 4 * (k4 - 96);
        }
        g_W4[i] = make_float4(src[0], src[1], src[2], src[3]);
        return;
    }
}

// panel start offsets (float4 units) in the packed off-diag triangle
#define OFFP0 0
#define OFFP1 1792
#define OFFP2 3328
#define OFFP3 4608
#define OFFP4 5632
#define OFFP5 6400
#define OFFP6 6912
#define OFFD_TOT 7168

// ---------------- shared memory (~190 KB) ----------------
struct Smem {
    float4 offd[OFFD_TOT];        // 114.7 KB packed strictly-lower off-diag D11
    float  diagblk[8][32 * 33];   //  33.8 KB padded 32x32 diag blocks
    float  diagc[8][4][32];       //   4 KB packed 8x8 strictly-lower coefs
    float4 vals[448];             //   7 KB unified values: x[0,128) w[128,384) u[384,448)
    float4 bblk3[8][3][32];       //  12 KB per-panel, per-h partial handoff
    float  bvs[NVDIM];            //   1 KB staged bv
    float4 part[7][192];          //  21.5 KB phase-C partials
};

#define FMA4C(a0,a1,a2,a3,c,v) do {                       \
    a0 = fmaf((c), (v).x, a0); a1 = fmaf((c), (v).y, a1); \
    a2 = fmaf((c), (v).z, a2); a3 = fmaf((c), (v).w, a3); } while (0)

#define OFFDG2(g2) do {                                            \
    float4 c = cp[(g2) * W];                                       \
    const float4* wp = &s.vals[128 + base + 4 * (g2)];             \
    FMA4C(oa0, oa1, oa2, oa3, c.x, wp[0]);                         \
    FMA4C(oa0, oa1, oa2, oa3, c.y, wp[1]);                         \
    FMA4C(oa0, oa1, oa2, oa3, c.z, wp[2]);                         \
    FMA4C(oa0, oa1, oa2, oa3, c.w, wp[3]); } while (0)

__global__ void __launch_bounds__(NTHR, 1)
ren_kernel(const float* __restrict__ x0, const float* __restrict__ u,
           const float* __restrict__ D11,
           const float* __restrict__ bx, const float* __restrict__ bv,
           const float* __restrict__ by, float* __restrict__ out)
{
    extern __shared__ char smem_raw[];
    Smem& s = *reinterpret_cast<Smem*>(smem_raw);
    const int tid  = threadIdx.x;
    const int lane = tid & 31;
    const int wid  = tid >> 5;
    const int row0 = blockIdx.x * RPC;
    const int j    = tid & 255;   // v-feature owned in phases A/B
    const int h    = tid >> 8;    // 3-way split selector
    const int OFFP[8] = {OFFP0, OFFP1, OFFP2, OFFP3, OFFP4, OFFP5, OFFP6, OFFD_TOT};

    // ---- one-time staging ----
#pragma unroll
    for (int p = 0; p < 7; p++) {
        const int W = 224 - 32 * p;
        for (int i = tid; i < 8 * W; i += NTHR) {
            int g2 = i / W, jp = i - g2 * W;
            s.offd[OFFP[p] + i] = g_D11P[(p * 8 + g2) * NVDIM + (32 * (p + 1) + jp)];
        }
    }
    for (int i = tid; i < 8 * 32 * 32; i += NTHR) {   // padded diag blocks
        int p = i >> 10, l = (i >> 5) & 31, q = i & 31;
        s.diagblk[p][l * 33 + q] = D11[(size_t)(32 * p + l) * NVDIM + 32 * p + q];
    }
    if (tid < 32) {                 // packed 8x8 strictly-lower group coefs
        int blk = tid >> 2, g = tid & 3;
        int base = blk * 32 + g * 8, idx = 0;
        for (int ii = 1; ii < 8; ii++)
            for (int jj = 0; jj < ii; jj++)
                s.diagc[blk][g][idx++] = D11[(size_t)(base + ii) * NVDIM + (base + jj)];
    }
    for (int i = tid; i < RPC * NXDIM; i += NTHR) {   // initial state -> vals.x
        int r = i >> 7, k = i & 127;
        ((float*)&s.vals[k])[r] = x0[(size_t)(row0 + r) * NXDIM + k];
    }
    if (tid < NVDIM) s.bvs[tid] = bv[tid];

    // phase-C mapping: outputs (o, o+96), k-chunk q
    const int o  = tid % 96;
    const int cq = tid / 96;            // 0..7
    const int o2 = o + 96;
    const float bo0 = bx[o];                                     // o < 96 -> x
    const float bo1 = (o2 < 128) ? bx[o2] : by[o2 - 128];

    float ureg = 0.f;               // prefetch u(0)
    if (tid < 256) {
        int r = tid >> 6, k = tid & 63;
        ureg = u[((size_t)0 * BATCH + row0 + r) * NUDIM + k];
    }
    __syncthreads();

    float* yout = out + (size_t)BATCH * NXDIM;

    for (int t = 0; t < TSTEPS; t++) {
        if (tid < 256) {            // commit u(t) -> vals.u, prefetch u(t+1)
            int r = tid >> 6, k = tid & 63;
            ((float*)&s.vals[384 + k])[r] = ureg;
            int tn = (t + 1 < TSTEPS) ? t + 1 : t;
            ureg = u[((size_t)tn * BATCH + row0 + r) * NUDIM + k];
        }
        __syncthreads();            // (1) u + x(t) + all prev-step writes visible

        // ---- phase A (3-way k-split): partial of C1 x + D12 u, all 4 rows ----
        float pa0 = 0.f, pa1 = 0.f, pa2 = 0.f, pa3 = 0.f;
        if (h == 0) {
#pragma unroll 4
            for (int k4 = 0; k4 < 16; k4++) {
                float4 c = g_C1T4[k4 * NVDIM + j];
                const float4* v = &s.vals[4 * k4];
                FMA4C(pa0, pa1, pa2, pa3, c.x, v[0]);
                FMA4C(pa0, pa1, pa2, pa3, c.y, v[1]);
                FMA4C(pa0, pa1, pa2, pa3, c.z, v[2]);
                FMA4C(pa0, pa1, pa2, pa3, c.w, v[3]);
            }
        } else if (h == 1) {
#pragma unroll 4
            for (int k4 = 16; k4 < 32; k4++) {
                float4 c = g_C1T4[k4 * NVDIM + j];
                const float4* v = &s.vals[4 * k4];
                FMA4C(pa0, pa1, pa2, pa3, c.x, v[0]);
                FMA4C(pa0, pa1, pa2, pa3, c.y, v[1]);
                FMA4C(pa0, pa1, pa2, pa3, c.z, v[2]);
                FMA4C(pa0, pa1, pa2, pa3, c.w, v[3]);
            }
        } else {
#pragma unroll 4
            for (int k4 = 0; k4 < 16; k4++) {
                float4 c = g_D12T4[k4 * NVDIM + j];
                const float4* v = &s.vals[384 + 4 * k4];
                FMA4C(pa0, pa1, pa2, pa3, c.x, v[0]);
                FMA4C(pa0, pa1, pa2, pa3, c.y, v[1]);
                FMA4C(pa0, pa1, pa2, pa3, c.z, v[2]);
                FMA4C(pa0, pa1, pa2, pa3, c.w, v[3]);
            }
        }
        float oa0 = 0.f, oa1 = 0.f, oa2 = 0.f, oa3 = 0.f;  // off-diag partial

        // ---- phase B: blocked triangular ReLU equilibrium ----
#pragma unroll
        for (int p = 0; p < 8; p++) {
            const int base = p * 32;
            if (j >= base && j < base + 32)   // owner: write partial (pa + oa)
                s.bblk3[p][h][j - base] =
                    make_float4(pa0 + oa0, pa1 + oa1, pa2 + oa2, pa3 + oa3);
            __syncthreads();                       // B1: partials visible

            if (wid < 4) {                         // warp r solves row r
                const int r = wid;
                const float* dbp = &s.diagblk[p][lane * 33];
                float bval = ((const float*)&s.bblk3[p][0][lane])[r]
                           + ((const float*)&s.bblk3[p][1][lane])[r]
                           + ((const float*)&s.bblk3[p][2][lane])[r]
                           + s.bvs[base + lane];
                float wmine = 0.f;
#pragma unroll
                for (int g = 0; g < 4; g++) {
                    const int q0 = g * 8;
                    float cg[28];
#pragma unroll
                    for (int q = 0; q < 28; q++) cg[q] = s.diagc[p][g][q];
                    float bg[8];
#pragma unroll
                    for (int q = 0; q < 8; q++)
                        bg[q] = __shfl_sync(0xffffffffu, bval, q0 + q);
                    float wloc[8];
#pragma unroll
                    for (int jj = 0; jj < 8; jj++) {   // redundant serial resolve
                        float wj = fmaxf(bg[jj], 0.f);
                        wloc[jj] = wj;
#pragma unroll
                        for (int ii = jj + 1; ii < 8; ii++)
                            bg[ii] = fmaf(cg[ii * (ii - 1) / 2 + jj], wj, bg[ii]);
                    }
                    if ((lane >> 3) == g) wmine = wloc[lane & 7];
                    float a0 = 0.f, a1 = 0.f;          // apply (upper coefs are 0)
                    a0 = fmaf(dbp[q0 + 0], wloc[0], a0); a1 = fmaf(dbp[q0 + 1], wloc[1], a1);
                    a0 = fmaf(dbp[q0 + 2], wloc[2], a0); a1 = fmaf(dbp[q0 + 3], wloc[3], a1);
                    a0 = fmaf(dbp[q0 + 4], wloc[4], a0); a1 = fmaf(dbp[q0 + 5], wloc[5], a1);
                    a0 = fmaf(dbp[q0 + 6], wloc[6], a0); a1 = fmaf(dbp[q0 + 7], wloc[7], a1);
                    bval += a0 + a1;
                }
                ((float*)&s.vals[128 + base + lane])[r] = wmine;   // w -> vals
            }
            __syncthreads();                       // B2: w(p) visible

            if (j >= base + 32) {                  // consumer: h's g2 subset
                const int W = 224 - 32 * p;
                const float4* cp = s.offd + OFFP[p] + (j - base - 32);
                if (h == 2) { OFFDG2(6); OFFDG2(7); }
                else { int g0 = 3 * h; OFFDG2(g0); OFFDG2(g0 + 1); OFFDG2(g0 + 2); }
            }
        }

        // ---- phase C: unified GEMM, 2 outputs x 14 k4 per thread ----
        float xa0, xa1, xa2, xa3, yb0, yb1, yb2, yb3;
        xa0 = xa1 = xa2 = xa3 = (cq == 0) ? bo0 : 0.f;
        yb0 = yb1 = yb2 = yb3 = (cq == 0) ? bo1 : 0.f;
#pragma unroll 7
        for (int i = 0; i < 14; i++) {
            const int k4 = cq * 14 + i;
            const float4* v = &s.vals[4 * k4];
            float4 v0 = v[0], v1 = v[1], v2 = v[2], v3 = v[3];
            float4 wa = g_W4[k4 * 192 + o];
            float4 wb = g_W4[k4 * 192 + o2];
            FMA4C(xa0, xa1, xa2, xa3, wa.x, v0);
            FMA4C(xa0, xa1, xa2, xa3, wa.y, v1);
            FMA4C(xa0, xa1, xa2, xa3, wa.z, v2);
            FMA4C(xa0, xa1, xa2, xa3, wa.w, v3);
            FMA4C(yb0, yb1, yb2, yb3, wb.x, v0);
            FMA4C(yb0, yb1, yb2, yb3, wb.y, v1);
            FMA4C(yb0, yb1, yb2, yb3, wb.z, v2);
            FMA4C(yb0, yb1, yb2, yb3, wb.w, v3);
        }
        if (cq > 0) {
            s.part[cq - 1][o]  = make_float4(xa0, xa1, xa2, xa3);
            s.part[cq - 1][o2] = make_float4(yb0, yb1, yb2, yb3);
        }
        __syncthreads();                       // (3) partials + all vals reads done

        // ---- combine (chunk-0 threads own outputs o and o2) ----
        if (cq == 0) {
#pragma unroll
            for (int pq = 0; pq < 7; pq++) {
                float4 pA = s.part[pq][o];
                float4 pB = s.part[pq][o2];
                xa0 += pA.x; xa1 += pA.y; xa2 += pA.z; xa3 += pA.w;
                yb0 += pB.x; yb1 += pB.y; yb2 += pB.z; yb3 += pB.w;
            }
            s.vals[o] = make_float4(xa0, xa1, xa2, xa3);   // x(t+1), o < 96
            if (o2 < 128) {
                s.vals[o2] = make_float4(yb0, yb1, yb2, yb3);
            } else {
                const int yo = o2 - 128;
                float* yp = yout + ((size_t)t * BATCH + row0) * NYDIM + yo;
                yp[0 * NYDIM] = yb0;
                yp[1 * NYDIM] = yb1;
                yp[2 * NYDIM] = yb2;
                yp[3 * NYDIM] = yb3;
            }
        }
    }

    // ---- final state x1 ----
    __syncthreads();
    if (tid < NXDIM) {
        float4 v = s.vals[tid];
        out[(size_t)(row0 + 0) * NXDIM + tid] = v.x;
        out[(size_t)(row0 + 1) * NXDIM + tid] = v.y;
        out[(size_t)(row0 + 2) * NXDIM + tid] = v.z;
        out[(size_t)(row0 + 3) * NXDIM + tid] = v.w;
    }
}

extern "C" void kernel_launch(void* const* d_in, const int* in_sizes, int n_in,
                              void* d_out, int out_size)
{
    const float* x0  = (const float*)d_in[0];
    const float* u   = (const float*)d_in[1];
    const float* A   = (const float*)d_in[2];
    const float* B1  = (const float*)d_in[3];
    const float* B2  = (const float*)d_in[4];
    const float* C1  = (const float*)d_in[5];
    const float* C2  = (const float*)d_in[6];
    const float* D11 = (const float*)d_in[7];
    const float* D12 = (const float*)d_in[8];
    const float* D21 = (const float*)d_in[9];
    const float* D22 = (const float*)d_in[10];
    const float* bx  = (const float*)d_in[11];
    const float* bv  = (const float*)d_in[12];
    const float* by  = (const float*)d_in[13];
    float* out = (float*)d_out;

    // id-space: 8192 (C1) + 4096 (D12) + 16384 (D11P) + 21504 (W4) = 50176
    prep_kernel<<<196, 256>>>(A, B1, B2, C1, C2, D11, D12, D21, D22);

    size_t smem = sizeof(Smem);
    cudaFuncSetAttribute(ren_kernel, cudaFuncAttributeMaxDynamicSharedMemorySize,
                         (int)smem);
    ren_kernel<<<NCTA, NTHR, smem>>>(x0, u, D11, bx, bv, by, out);
}

// round 16
// speedup vs baseline: 1.2588x; 1.0427x over previous
#include <cuda_runtime.h>
#include <cstddef>

#define TSTEPS 512
#define BATCH  512
#define NUDIM  64
#define NXDIM  128
#define NVDIM  256
#define NYDIM  64
#define RPC    4
#define NCTA   128
#define NTHR   768

// ---------------- packed weights (built once per launch) ----------
__device__ float4 g_C1T4 [32 * NVDIM];   // C1T4[k4*256+j].q = C1[j][4k4+q]
__device__ float4 g_D12T4[16 * NVDIM];
__device__ float4 g_D11P [64 * NVDIM];   // D11P[g*256+j].q = D11[j][4g+q]
__device__ float4 g_W4   [112 * 192];    // unified phase-C weights [k4][output]

__global__ void prep_kernel(const float* __restrict__ A,  const float* __restrict__ B1,
                            const float* __restrict__ B2, const float* __restrict__ C1,
                            const float* __restrict__ C2, const float* __restrict__ D11,
                            const float* __restrict__ D12,const float* __restrict__ D21,
                            const float* __restrict__ D22)
{
    int id = blockIdx.x * blockDim.x + threadIdx.x;
    int off = 0;
#define XP4(dst, src, J, K)                                                  \
    if (id < off + (J) * (K) / 4) {                                          \
        int i = id - off; int k4 = i / (J); int j = i % (J);                 \
        const float* p = (src) + (size_t)j * (K) + 4 * k4;                   \
        dst[i] = make_float4(p[0], p[1], p[2], p[3]); return;                \
    } off += (J) * (K) / 4;
    XP4(g_C1T4,  C1,  NVDIM, NXDIM)
    XP4(g_D12T4, D12, NVDIM, NUDIM)
    XP4(g_D11P,  D11, NVDIM, NVDIM)
#undef XP4
    if (id < off + 112 * 192) {          // unified phase-C weights
        int i = id - off; int k4 = i / 192; int o = i % 192;
        const float* src;
        if (o < 128) {                   // x outputs: A | B1 | B2 over k
            if (k4 < 32)      src = A   + (size_t)o * NXDIM + 4 * k4;
            else if (k4 < 96) src = B1  + (size_t)o * NVDIM + 4 * (k4 - 32);
            else              src = B2  + (size_t)o * NUDIM + 4 * (k4 - 96);
        } else {                         // y outputs: C2 | D21 | D22
            int yo = o - 128;
            if (k4 < 32)      src = C2  + (size_t)yo * NXDIM + 4 * k4;
            else if (k4 < 96) src = D21 + (size_t)yo * NVDIM + 4 * (k4 - 32);
            else              src = D22 + (size_t)yo * NUDIM + 4 * (k4 - 96);
        }
        g_W4[i] = make_float4(src[0], src[1], src[2], src[3]);
        return;
    }
}

// panel start offsets (float4 units) in the packed off-diag triangle
#define OFFP0 0
#define OFFP1 1792
#define OFFP2 3328
#define OFFP3 4608
#define OFFP4 5632
#define OFFP5 6400
#define OFFP6 6912
#define OFFD_TOT 7168

// ---------------- shared memory (~190 KB) ----------------
struct Smem {
    float4 offd[OFFD_TOT];        // 114.7 KB packed strictly-lower off-diag D11
    float  diagblk[8][32 * 33];   //  33.8 KB padded 32x32 diag blocks
    float  diagc[8][4][32];       //   4 KB packed 8x8 strictly-lower coefs
    float4 vals[448];             //   7 KB unified values: x[0,128) w[128,384) u[384,448)
    float4 bblk3[8][3][32];       //  12 KB per-panel, per-h partial handoff
    float  bvs[NVDIM];            //   1 KB staged bv
    float4 part[7][192];          //  21.5 KB phase-C partials
};

#define FMA4C(a0,a1,a2,a3,c,v) do {                       \
    a0 = fmaf((c), (v).x, a0); a1 = fmaf((c), (v).y, a1); \
    a2 = fmaf((c), (v).z, a2); a3 = fmaf((c), (v).w, a3); } while (0)

// apply one g2 unit of panel coefs (pointer cp, row-width W) with w at vals[wb..]
#define OFFDG2W(g2, W, wb) do {                                    \
    float4 c = cp[(g2) * (W)];                                     \
    const float4* wp = &s.vals[(wb) + 4 * (g2)];                   \
    FMA4C(oa0, oa1, oa2, oa3, c.x, wp[0]);                         \
    FMA4C(oa0, oa1, oa2, oa3, c.y, wp[1]);                         \
    FMA4C(oa0, oa1, oa2, oa3, c.z, wp[2]);                         \
    FMA4C(oa0, oa1, oa2, oa3, c.w, wp[3]); } while (0)

__global__ void __launch_bounds__(NTHR, 1)
ren_kernel(const float* __restrict__ x0, const float* __restrict__ u,
           const float* __restrict__ D11,
           const float* __restrict__ bx, const float* __restrict__ bv,
           const float* __restrict__ by, float* __restrict__ out)
{
    extern __shared__ char smem_raw[];
    Smem& s = *reinterpret_cast<Smem*>(smem_raw);
    const int tid  = threadIdx.x;
    const int lane = tid & 31;
    const int wid  = tid >> 5;
    const int row0 = blockIdx.x * RPC;
    const int j    = tid & 255;   // v-feature owned in phases A/B
    const int h    = tid >> 8;    // 3-way split selector
    const int OFFP[8] = {OFFP0, OFFP1, OFFP2, OFFP3, OFFP4, OFFP5, OFFP6, OFFD_TOT};

    // ---- one-time staging ----
#pragma unroll
    for (int p = 0; p < 7; p++) {
        const int W = 224 - 32 * p;
        for (int i = tid; i < 8 * W; i += NTHR) {
            int g2 = i / W, jp = i - g2 * W;
            s.offd[OFFP[p] + i] = g_D11P[(p * 8 + g2) * NVDIM + (32 * (p + 1) + jp)];
        }
    }
    for (int i = tid; i < 8 * 32 * 32; i += NTHR) {   // padded diag blocks
        int p = i >> 10, l = (i >> 5) & 31, q = i & 31;
        s.diagblk[p][l * 33 + q] = D11[(size_t)(32 * p + l) * NVDIM + 32 * p + q];
    }
    if (tid < 32) {                 // packed 8x8 strictly-lower group coefs
        int blk = tid >> 2, g = tid & 3;
        int base = blk * 32 + g * 8, idx = 0;
        for (int ii = 1; ii < 8; ii++)
            for (int jj = 0; jj < ii; jj++)
                s.diagc[blk][g][idx++] = D11[(size_t)(base + ii) * NVDIM + (base + jj)];
    }
    for (int i = tid; i < RPC * NXDIM; i += NTHR) {   // initial state -> vals.x
        int r = i >> 7, k = i & 127;
        ((float*)&s.vals[k])[r] = x0[(size_t)(row0 + r) * NXDIM + k];
    }
    if (tid < NVDIM) s.bvs[tid] = bv[tid];

    // phase-C mapping: outputs (o, o+96), k-chunk cq
    const int o  = tid % 96;
    const int cq = tid / 96;            // 0..7
    const int o2 = o + 96;
    const float bo0 = bx[o];
    const float bo1 = (o2 < 128) ? bx[o2] : by[o2 - 128];

    float ureg = 0.f;               // prefetch u(0)
    if (tid < 256) {
        int r = tid >> 6, k = tid & 63;
        ureg = u[((size_t)0 * BATCH + row0 + r) * NUDIM + k];
    }
    __syncthreads();

    float* yout = out + (size_t)BATCH * NXDIM;

    for (int t = 0; t < TSTEPS; t++) {
        if (tid < 256) {            // commit u(t) -> vals.u, prefetch u(t+1)
            int r = tid >> 6, k = tid & 63;
            ((float*)&s.vals[384 + k])[r] = ureg;
            int tn = (t + 1 < TSTEPS) ? t + 1 : t;
            ureg = u[((size_t)tn * BATCH + row0 + r) * NUDIM + k];
        }
        __syncthreads();            // (1) u + x(t) + all prev-step writes visible

        // ---- phase A (3-way k-split): partial of C1 x + D12 u, all 4 rows ----
        float pa0 = 0.f, pa1 = 0.f, pa2 = 0.f, pa3 = 0.f;
        if (h == 0) {
#pragma unroll 4
            for (int k4 = 0; k4 < 16; k4++) {
                float4 c = g_C1T4[k4 * NVDIM + j];
                const float4* v = &s.vals[4 * k4];
                FMA4C(pa0, pa1, pa2, pa3, c.x, v[0]);
                FMA4C(pa0, pa1, pa2, pa3, c.y, v[1]);
                FMA4C(pa0, pa1, pa2, pa3, c.z, v[2]);
                FMA4C(pa0, pa1, pa2, pa3, c.w, v[3]);
            }
        } else if (h == 1) {
#pragma unroll 4
            for (int k4 = 16; k4 < 32; k4++) {
                float4 c = g_C1T4[k4 * NVDIM + j];
                const float4* v = &s.vals[4 * k4];
                FMA4C(pa0, pa1, pa2, pa3, c.x, v[0]);
                FMA4C(pa0, pa1, pa2, pa3, c.y, v[1]);
                FMA4C(pa0, pa1, pa2, pa3, c.z, v[2]);
                FMA4C(pa0, pa1, pa2, pa3, c.w, v[3]);
            }
        } else {
#pragma unroll 4
            for (int k4 = 0; k4 < 16; k4++) {
                float4 c = g_D12T4[k4 * NVDIM + j];
                const float4* v = &s.vals[384 + 4 * k4];
                FMA4C(pa0, pa1, pa2, pa3, c.x, v[0]);
                FMA4C(pa0, pa1, pa2, pa3, c.y, v[1]);
                FMA4C(pa0, pa1, pa2, pa3, c.z, v[2]);
                FMA4C(pa0, pa1, pa2, pa3, c.w, v[3]);
            }
        }
        float oa0 = 0.f, oa1 = 0.f, oa2 = 0.f, oa3 = 0.f;  // off-diag partial

        // pre-handoff: panel 0 (no off-diag contributions yet)
        if (j < 32)
            s.bblk3[0][h][j] = make_float4(pa0, pa1, pa2, pa3);
        __syncthreads();                           // B0: bblk[0] visible

        // ---- phase B: one barrier per panel; solver adds subdiag via shfl ----
        float wprev = 0.f;
#pragma unroll
        for (int p = 0; p < 8; p++) {
            const int base = p * 32;
            if (wid < 4) {                         // warp r solves row r
                const int r = wid;
                const float* dbp = &s.diagblk[p][lane * 33];
                float bval = ((const float*)&s.bblk3[p][0][lane])[r]
                           + ((const float*)&s.bblk3[p][1][lane])[r]
                           + ((const float*)&s.bblk3[p][2][lane])[r]
                           + s.bvs[base + lane];
                if (p > 0) {                       // deferred subdiag w(p-1)
                    const int Wm = 224 - 32 * (p - 1);
                    const float4* sp = s.offd + OFFP[p - 1] + lane;
#pragma unroll
                    for (int g2 = 0; g2 < 8; g2++) {
                        float4 c = sp[g2 * Wm];
                        bval = fmaf(c.x, __shfl_sync(0xffffffffu, wprev, 4 * g2 + 0), bval);
                        bval = fmaf(c.y, __shfl_sync(0xffffffffu, wprev, 4 * g2 + 1), bval);
                        bval = fmaf(c.z, __shfl_sync(0xffffffffu, wprev, 4 * g2 + 2), bval);
                        bval = fmaf(c.w, __shfl_sync(0xffffffffu, wprev, 4 * g2 + 3), bval);
                    }
                }
                float wmine = 0.f;
#pragma unroll
                for (int g = 0; g < 4; g++) {
                    const int q0 = g * 8;
                    float cg[28];
#pragma unroll
                    for (int q = 0; q < 28; q++) cg[q] = s.diagc[p][g][q];
                    float bg[8];
#pragma unroll
                    for (int q = 0; q < 8; q++)
                        bg[q] = __shfl_sync(0xffffffffu, bval, q0 + q);
                    float wloc[8];
#pragma unroll
                    for (int jj = 0; jj < 8; jj++) {   // redundant serial resolve
                        float wj = fmaxf(bg[jj], 0.f);
                        wloc[jj] = wj;
#pragma unroll
                        for (int ii = jj + 1; ii < 8; ii++)
                            bg[ii] = fmaf(cg[ii * (ii - 1) / 2 + jj], wj, bg[ii]);
                    }
                    if ((lane >> 3) == g) wmine = wloc[lane & 7];
                    float a0 = 0.f, a1 = 0.f;          // apply (upper coefs are 0)
                    a0 = fmaf(dbp[q0 + 0], wloc[0], a0); a1 = fmaf(dbp[q0 + 1], wloc[1], a1);
                    a0 = fmaf(dbp[q0 + 2], wloc[2], a0); a1 = fmaf(dbp[q0 + 3], wloc[3], a1);
                    a0 = fmaf(dbp[q0 + 4], wloc[4], a0); a1 = fmaf(dbp[q0 + 5], wloc[5], a1);
                    a0 = fmaf(dbp[q0 + 6], wloc[6], a0); a1 = fmaf(dbp[q0 + 7], wloc[7], a1);
                    bval += a0 + a1;
                }
                ((float*)&s.vals[128 + base + lane])[r] = wmine;   // w -> vals
                wprev = wmine;
            }

            // consumers: apply w(p-1) for all rows past the subdiag block
            if (p > 0 && j >= base + 32) {
                const int Wm = 224 - 32 * (p - 1);
                const int wb = 128 + base - 32;        // w(p-1) in vals
                const float4* cp = s.offd + OFFP[p - 1] + (j - base);
                if (h == 2) { OFFDG2W(6, Wm, wb); OFFDG2W(7, Wm, wb); }
                else {
                    int g0 = 3 * h;
                    OFFDG2W(g0, Wm, wb); OFFDG2W(g0 + 1, Wm, wb); OFFDG2W(g0 + 2, Wm, wb);
                }
            }
            // owner of panel p+1 hands off (contributions through p-1; solver adds p)
            if (p < 7 && j >= base + 32 && j < base + 64)
                s.bblk3[p + 1][h][j - base - 32] =
                    make_float4(pa0 + oa0, pa1 + oa1, pa2 + oa2, pa3 + oa3);
            __syncthreads();                       // w(p) + bblk[p+1] visible
        }

        // ---- phase C: unified GEMM, 2 outputs x 14 k4 per thread ----
        float xa0, xa1, xa2, xa3, yb0, yb1, yb2, yb3;
        xa0 = xa1 = xa2 = xa3 = (cq == 0) ? bo0 : 0.f;
        yb0 = yb1 = yb2 = yb3 = (cq == 0) ? bo1 : 0.f;
#pragma unroll 7
        for (int i = 0; i < 14; i++) {
            const int k4 = cq * 14 + i;
            const float4* v = &s.vals[4 * k4];
            float4 v0 = v[0], v1 = v[1], v2 = v[2], v3 = v[3];
            float4 wa = g_W4[k4 * 192 + o];
            float4 wb = g_W4[k4 * 192 + o2];
            FMA4C(xa0, xa1, xa2, xa3, wa.x, v0);
            FMA4C(xa0, xa1, xa2, xa3, wa.y, v1);
            FMA4C(xa0, xa1, xa2, xa3, wa.z, v2);
            FMA4C(xa0, xa1, xa2, xa3, wa.w, v3);
            FMA4C(yb0, yb1, yb2, yb3, wb.x, v0);
            FMA4C(yb0, yb1, yb2, yb3, wb.y, v1);
            FMA4C(yb0, yb1, yb2, yb3, wb.z, v2);
            FMA4C(yb0, yb1, yb2, yb3, wb.w, v3);
        }
        if (cq > 0) {
            s.part[cq - 1][o]  = make_float4(xa0, xa1, xa2, xa3);
            s.part[cq - 1][o2] = make_float4(yb0, yb1, yb2, yb3);
        }
        __syncthreads();                       // (3) partials + vals reads done

        // ---- combine (chunk-0 threads own outputs o and o2) ----
        if (cq == 0) {
#pragma unroll
            for (int pq = 0; pq < 7; pq++) {
                float4 pA = s.part[pq][o];
                float4 pB = s.part[pq][o2];
                xa0 += pA.x; xa1 += pA.y; xa2 += pA.z; xa3 += pA.w;
                yb0 += pB.x; yb1 += pB.y; yb2 += pB.z; yb3 += pB.w;
            }
            s.vals[o] = make_float4(xa0, xa1, xa2, xa3);   // x(t+1), o < 96
            if (o2 < 128) {
                s.vals[o2] = make_float4(yb0, yb1, yb2, yb3);
            } else {
                const int yo = o2 - 128;
                float* yp = yout + ((size_t)t * BATCH + row0) * NYDIM + yo;
                yp[0 * NYDIM] = yb0;
                yp[1 * NYDIM] = yb1;
                yp[2 * NYDIM] = yb2;
                yp[3 * NYDIM] = yb3;
            }
        }
    }

    // ---- final state x1 ----
    __syncthreads();
    if (tid < NXDIM) {
        float4 v = s.vals[tid];
        out[(size_t)(row0 + 0) * NXDIM + tid] = v.x;
        out[(size_t)(row0 + 1) * NXDIM + tid] = v.y;
        out[(size_t)(row0 + 2) * NXDIM + tid] = v.z;
        out[(size_t)(row0 + 3) * NXDIM + tid] = v.w;
    }
}

extern "C" void kernel_launch(void* const* d_in, const int* in_sizes, int n_in,
                              void* d_out, int out_size)
{
    const float* x0  = (const float*)d_in[0];
    const float* u   = (const float*)d_in[1];
    const float* A   = (const float*)d_in[2];
    const float* B1  = (const float*)d_in[3];
    const float* B2  = (const float*)d_in[4];
    const float* C1  = (const float*)d_in[5];
    const float* C2  = (const float*)d_in[6];
    const float* D11 = (const float*)d_in[7];
    const float* D12 = (const float*)d_in[8];
    const float* D21 = (const float*)d_in[9];
    const float* D22 = (const float*)d_in[10];
    const float* bx  = (const float*)d_in[11];
    const float* bv  = (const float*)d_in[12];
    const float* by  = (const float*)d_in[13];
    float* out = (float*)d_out;

    prep_kernel<<<196, 256>>>(A, B1, B2, C1, C2, D11, D12, D21, D22);

    size_t smem = sizeof(Smem);
    cudaFuncSetAttribute(ren_kernel, cudaFuncAttributeMaxDynamicSharedMemorySize,
                         (int)smem);
    ren_kernel<<<NCTA, NTHR, smem>>>(x0, u, D11, bx, bv, by, out);
}